// round 1
// baseline (speedup 1.0000x reference)
#include <cuda_runtime.h>

// cAttend_simple: out = val * (1 + fx),
//   fx[b,j] = SCALE * ( (Wk^T (Wq u_b + bq V_b)) . embed[pos_bj] + (Wq u_b + bq V_b) . bk )
// where u_b = sum_i val[b,i] * embed[pos[b,i]],  V_b = sum_i val[b,i].

#define BB 4
#define NN 4096
#define EE 256
#define DD 64
#define CHUNKS 64
#define ROWS (NN / CHUNKS)   // 64 rows per chunk
#define SCALE 0.125f         // 64^{-1/2}

// Deterministic scratch (no atomics -> bitwise-reproducible across graph replays)
__device__ float g_part[BB][CHUNKS][EE];   // partial u sums
__device__ float g_vpart[BB][CHUNKS];      // partial V sums
__device__ float g_w[BB][EE];              // Wk^T s
__device__ float g_c[BB];                  // s . bk

// ---------------------------------------------------------------------------
// Kernel A: per (batch, chunk) partial weighted gather-sum of embed rows.
// grid (CHUNKS, BB), block EE=256 threads; thread t owns embedding column t.
// ---------------------------------------------------------------------------
__global__ void __launch_bounds__(EE) k_accum(const float* __restrict__ val,
                                              const int* __restrict__ pos,
                                              const float* __restrict__ embed) {
    const int b = blockIdx.y;
    const int ch = blockIdx.x;
    const int t = threadIdx.x;
    const int r0 = ch * ROWS;

    __shared__ int   sp[ROWS];
    __shared__ float sv[ROWS];
    if (t < ROWS) {
        sp[t] = pos[b * NN + r0 + t];
        sv[t] = val[b * NN + r0 + t];
    }
    __syncthreads();

    float acc = 0.f;
#pragma unroll 8
    for (int i = 0; i < ROWS; i++) {
        acc += sv[i] * __ldg(&embed[(size_t)sp[i] * EE + t]);
    }
    g_part[b][ch][t] = acc;

    if (t < 32) {
        float s = 0.f;
        for (int i = t; i < ROWS; i += 32) s += sv[i];
#pragma unroll
        for (int o = 16; o; o >>= 1) s += __shfl_xor_sync(0xffffffffu, s, o);
        if (t == 0) g_vpart[b][ch] = s;
    }
}

// ---------------------------------------------------------------------------
// Kernel B: reduce partials (fixed order) and do the two tiny matvecs.
// grid BB, block EE=256 threads. Cost is negligible (~10K FMAs / block).
// ---------------------------------------------------------------------------
__global__ void __launch_bounds__(EE) k_project(const float* __restrict__ Wq,
                                                const float* __restrict__ bq,
                                                const float* __restrict__ Wk,
                                                const float* __restrict__ bk) {
    const int b = blockIdx.x;
    const int t = threadIdx.x;

    __shared__ float u[EE];
    __shared__ float s[DD];
    __shared__ float Vsh;

    // u[t] = sum over chunks (fixed order -> deterministic), coalesced over t
    float acc = 0.f;
#pragma unroll 8
    for (int c = 0; c < CHUNKS; c++) acc += g_part[b][c][t];
    u[t] = acc;

    if (t == 0) {
        float V = 0.f;
        for (int c = 0; c < CHUNKS; c++) V += g_vpart[b][c];
        Vsh = V;
    }
    __syncthreads();

    // s = Wq u + bq * V   (64 outputs, one thread each)
    if (t < DD) {
        float a = bq[t] * Vsh;
#pragma unroll 8
        for (int e = 0; e < EE; e++) a += Wq[t * EE + e] * u[e];
        s[t] = a;
    }
    __syncthreads();

    // w[t] = sum_d Wk[d][t] * s[d]   (coalesced over t)
    float w = 0.f;
#pragma unroll 8
    for (int d = 0; d < DD; d++) w += Wk[d * EE + t] * s[d];
    g_w[b][t] = w;

    // c = s . bk
    if (t < 32) {
        float c = 0.f;
        for (int d = t; d < DD; d += 32) c += s[d] * bk[d];
#pragma unroll
        for (int o = 16; o; o >>= 1) c += __shfl_xor_sync(0xffffffffu, c, o);
        if (t == 0) g_c[b] = c;
    }
}

// ---------------------------------------------------------------------------
// Kernel C: out[b,j] = val * (1 + SCALE*(w . embed[pos] + c)).
// One warp per output row; 8 floats (2 x float4) per lane -> full 256-dot.
// grid (64, BB), block 256 (8 warps) -> each warp does 8 rows.
// ---------------------------------------------------------------------------
__global__ void __launch_bounds__(256) k_out(const float* __restrict__ val,
                                             const int* __restrict__ pos,
                                             const float* __restrict__ embed,
                                             float* __restrict__ out) {
    const int b = blockIdx.y;
    const int t = threadIdx.x;

    __shared__ float ws[EE];
    __shared__ float cs;
    ws[t] = g_w[b][t];
    if (t == 0) cs = g_c[b];
    __syncthreads();

    const int warp = t >> 5;
    const int lane = t & 31;
    const float4 w0 = reinterpret_cast<const float4*>(ws)[lane];
    const float4 w1 = reinterpret_cast<const float4*>(ws)[lane + 32];

    for (int r = blockIdx.x * 8 + warp; r < NN; r += gridDim.x * 8) {
        const int p = pos[b * NN + r];  // uniform across warp (broadcast load)
        const float4* er = reinterpret_cast<const float4*>(embed + (size_t)p * EE);
        const float4 a0 = __ldg(&er[lane]);
        const float4 a1 = __ldg(&er[lane + 32]);
        float dot = a0.x * w0.x + a0.y * w0.y + a0.z * w0.z + a0.w * w0.w
                  + a1.x * w1.x + a1.y * w1.y + a1.z * w1.z + a1.w * w1.w;
#pragma unroll
        for (int o = 16; o; o >>= 1) dot += __shfl_xor_sync(0xffffffffu, dot, o);
        if (lane == 0) {
            const float v = val[b * NN + r];
            out[b * NN + r] = v + v * (SCALE * (dot + cs));
        }
    }
}

// ---------------------------------------------------------------------------
extern "C" void kernel_launch(void* const* d_in, const int* in_sizes, int n_in,
                              void* d_out, int out_size) {
    // metadata order: t, val, pos, embed, Wq, bq, Wk, bk
    // (be robust to the scalar 't' being dropped: last 7 inputs are fixed)
    const int base = n_in - 7;
    const float* val   = (const float*)d_in[base + 0];
    const int*   pos   = (const int*)  d_in[base + 1];
    const float* embed = (const float*)d_in[base + 2];
    const float* Wq    = (const float*)d_in[base + 3];
    const float* bq    = (const float*)d_in[base + 4];
    const float* Wk    = (const float*)d_in[base + 5];
    const float* bk    = (const float*)d_in[base + 6];
    float* out = (float*)d_out;

    k_accum<<<dim3(CHUNKS, BB), EE>>>(val, pos, embed);
    k_project<<<BB, EE>>>(Wq, bq, Wk, bk);
    k_out<<<dim3(64, BB), 256>>>(val, pos, embed, out);
}

// round 3
// speedup vs baseline: 1.9025x; 1.9025x over previous
#include <cuda_runtime.h>

// cAttend_simple collapsed algebraically:
//   out[b,j] = val[b,j] * (1 + SCALE * (w_b . embed[pos[b,j]] + c_b))
//   where s_b = Wq u_b + bq V_b,  u_b = sum_i val[b,i] embed[pos[b,i]],  V_b = sum_i val[b,i]
//         w_b = Wk^T s_b,  c_b = s_b . bk

#define BB 4
#define NN 4096
#define EE 256
#define DD 64
#define CHUNKS 256
#define ROWS 16              // rows per chunk (NN / CHUNKS)
#define SCALE 0.125f         // 64^{-1/2}

// Deterministic scratch (no atomics -> bitwise-reproducible across graph replays)
__device__ float4 g_part4[BB][CHUNKS][EE / 4];  // partial u sums, float4 layout
__device__ float  g_vpart[BB][CHUNKS];          // partial V sums
__device__ float  g_w[BB][EE];                  // Wk^T s
__device__ float  g_c[BB];                      // s . bk

// ---------------------------------------------------------------------------
// Kernel A: per (batch, chunk) weighted gather-sum of 16 embed rows.
// grid (CHUNKS, BB) = 1024 blocks, block 256 threads.
// Thread layout: group g = t/64 handles rows [4g, 4g+4), lane l = t%64 owns
// one float4 column-quad. 4 independent LDG.128 chains per thread.
// ---------------------------------------------------------------------------
__global__ void __launch_bounds__(256) k_accum(const float* __restrict__ val,
                                               const int* __restrict__ pos,
                                               const float* __restrict__ embed) {
    const int b  = blockIdx.y;
    const int ch = blockIdx.x;
    const int t  = threadIdx.x;
    const int g  = t >> 6;
    const int l  = t & 63;

    __shared__ int    sp[ROWS];
    __shared__ float  sv[ROWS];
    __shared__ float4 red[4][64];

    if (t < ROWS) {
        sp[t] = pos[b * NN + ch * ROWS + t];
        sv[t] = val[b * NN + ch * ROWS + t];
    }
    __syncthreads();

    float4 acc = make_float4(0.f, 0.f, 0.f, 0.f);
#pragma unroll
    for (int i = 0; i < 4; i++) {
        const int r = g * 4 + i;
        const float4* e = reinterpret_cast<const float4*>(embed + (size_t)sp[r] * EE);
        const float4 a = __ldg(&e[l]);
        const float  v = sv[r];
        acc.x += v * a.x; acc.y += v * a.y; acc.z += v * a.z; acc.w += v * a.w;
    }
    red[g][l] = acc;
    __syncthreads();

    if (g == 0) {
        float4 s = red[0][l];
        const float4 s1 = red[1][l], s2 = red[2][l], s3 = red[3][l];
        s.x += s1.x + s2.x + s3.x;
        s.y += s1.y + s2.y + s3.y;
        s.z += s1.z + s2.z + s3.z;
        s.w += s1.w + s2.w + s3.w;
        g_part4[b][ch][l] = s;
    }
    if (t == 64) {  // one thread of group 1: 16 serial adds, trivial
        float s = 0.f;
#pragma unroll
        for (int i = 0; i < ROWS; i++) s += sv[i];
        g_vpart[b][ch] = s;
    }
}

// ---------------------------------------------------------------------------
// Kernel B: reduce partials (fixed order) + two tiny matvecs.
// grid BB, block 1024. Phase 1: 16-way split float4 reduction of 256 chunks.
// ---------------------------------------------------------------------------
__global__ void __launch_bounds__(1024) k_project(const float* __restrict__ Wq,
                                                  const float* __restrict__ bq,
                                                  const float* __restrict__ Wk,
                                                  const float* __restrict__ bk) {
    const int b    = blockIdx.x;
    const int tid  = threadIdx.x;
    const int q    = tid >> 6;   // 0..15
    const int l    = tid & 63;
    const int warp = tid >> 5;
    const int lane = tid & 31;

    __shared__ float4 red[16][64];
    __shared__ float  u[EE];
    __shared__ float  s[DD];
    __shared__ float  Vsh;

    // 16-way split reduce over chunks (fixed order within each split -> deterministic)
    float4 acc = make_float4(0.f, 0.f, 0.f, 0.f);
#pragma unroll
    for (int c = q; c < CHUNKS; c += 16) {
        const float4 a = g_part4[b][c][l];
        acc.x += a.x; acc.y += a.y; acc.z += a.z; acc.w += a.w;
    }
    red[q][l] = acc;

    // V reduce (warp 31)
    if (warp == 31) {
        float v = 0.f;
#pragma unroll
        for (int c = lane; c < CHUNKS; c += 32) v += g_vpart[b][c];
#pragma unroll
        for (int o = 16; o; o >>= 1) v += __shfl_xor_sync(0xffffffffu, v, o);
        if (lane == 0) Vsh = v;
    }
    __syncthreads();

    if (tid < 64) {
        float4 a = red[0][tid];
#pragma unroll
        for (int j = 1; j < 16; j++) {
            const float4 r = red[j][tid];
            a.x += r.x; a.y += r.y; a.z += r.z; a.w += r.w;
        }
        u[tid * 4 + 0] = a.x; u[tid * 4 + 1] = a.y;
        u[tid * 4 + 2] = a.z; u[tid * 4 + 3] = a.w;
    }
    __syncthreads();

    // s[d] = Wq[d,:] . u + bq[d] * V   -- 2 outputs per warp, coalesced Wq reads
#pragma unroll
    for (int d = warp; d < DD; d += 32) {
        float a = 0.f;
#pragma unroll
        for (int e = lane; e < EE; e += 32) a += Wq[d * EE + e] * u[e];
#pragma unroll
        for (int o = 16; o; o >>= 1) a += __shfl_xor_sync(0xffffffffu, a, o);
        if (lane == 0) s[d] = a + bq[d] * Vsh;
    }
    __syncthreads();

    // w[t] = sum_d Wk[d][t] * s[d]  (coalesced over t), and c = s . bk
    if (tid < EE) {
        float w = 0.f;
#pragma unroll 8
        for (int d = 0; d < DD; d++) w += Wk[d * EE + tid] * s[d];
        g_w[b][tid] = w;
    }
    if (warp == 30) {
        float c = s[lane] * bk[lane] + s[lane + 32] * bk[lane + 32];
#pragma unroll
        for (int o = 16; o; o >>= 1) c += __shfl_xor_sync(0xffffffffu, c, o);
        if (lane == 0) g_c[b] = c;
    }
}

// ---------------------------------------------------------------------------
// Kernel C: out[b,j] = val * (1 + SCALE*(w . embed[pos] + c)).
// grid (512, BB), block 256 = 8 warps, exactly one row per warp (no loop).
// ---------------------------------------------------------------------------
__global__ void __launch_bounds__(256) k_out(const float* __restrict__ val,
                                             const int* __restrict__ pos,
                                             const float* __restrict__ embed,
                                             float* __restrict__ out) {
    const int b = blockIdx.y;
    const int t = threadIdx.x;

    __shared__ float ws[EE];
    __shared__ float cs;
    ws[t] = g_w[b][t];
    if (t == 0) cs = g_c[b];
    __syncthreads();

    const int warp = t >> 5;
    const int lane = t & 31;
    const float4 w0 = reinterpret_cast<const float4*>(ws)[lane];
    const float4 w1 = reinterpret_cast<const float4*>(ws)[lane + 32];

    const int r = blockIdx.x * 8 + warp;
    const int p = pos[b * NN + r];                 // uniform across warp
    const float v = val[b * NN + r];               // issued early
    const float4* er = reinterpret_cast<const float4*>(embed + (size_t)p * EE);
    const float4 a0 = __ldg(&er[lane]);
    const float4 a1 = __ldg(&er[lane + 32]);
    float dot = a0.x * w0.x + a0.y * w0.y + a0.z * w0.z + a0.w * w0.w
              + a1.x * w1.x + a1.y * w1.y + a1.z * w1.z + a1.w * w1.w;
#pragma unroll
    for (int o = 16; o; o >>= 1) dot += __shfl_xor_sync(0xffffffffu, dot, o);
    if (lane == 0) {
        out[b * NN + r] = v + v * (SCALE * (dot + cs));
    }
}

// ---------------------------------------------------------------------------
extern "C" void kernel_launch(void* const* d_in, const int* in_sizes, int n_in,
                              void* d_out, int out_size) {
    // metadata order: t, val, pos, embed, Wq, bq, Wk, bk
    const int base = n_in - 7;
    const float* val   = (const float*)d_in[base + 0];
    const int*   pos   = (const int*)  d_in[base + 1];
    const float* embed = (const float*)d_in[base + 2];
    const float* Wq    = (const float*)d_in[base + 3];
    const float* bq    = (const float*)d_in[base + 4];
    const float* Wk    = (const float*)d_in[base + 5];
    const float* bk    = (const float*)d_in[base + 6];
    float* out = (float*)d_out;

    k_accum<<<dim3(CHUNKS, BB), 256>>>(val, pos, embed);
    k_project<<<BB, 1024>>>(Wq, bq, Wk, bk);
    k_out<<<dim3(512, BB), 256>>>(val, pos, embed, out);
}

// round 5
// speedup vs baseline: 2.0504x; 1.0777x over previous
#include <cuda_runtime.h>

// cAttend_simple collapsed algebraically:
//   out[b,j] = val[b,j] * (1 + SCALE*(w_b . embed[pos[b,j]] + c_b))
//   s_b = Wq u_b + bq V_b;  u_b = sum_i val[b,i] embed[pos[b,i]];  V_b = sum_i val[b,i]
//   w_b = Wk^T s_b;  c_b = s_b . bk
//
// Single persistent kernel: 128 blocks x 1024 threads (1 CTA/SM, all co-resident).
// Each block owns 128 rows of one batch; gathered embed rows are cached in smem
// so the second gather (phase 3) never touches global memory.

#define BB 4
#define NN 4096
#define EE 256
#define DD 64
#define NBLK 128           // persistent blocks (<=148 SMs -> all resident)
#define BPB  32            // blocks per batch
#define RPB  128           // rows per block
#define SCALE 0.125f       // 64^{-1/2}

// smem layout (bytes)
#define OFF_SROW 0                       // float4 srow[RPB][64]   131072
#define OFF_SP   131072                  // int   sp[RPB]          512
#define OFF_SV   (131072 + 512)          // float sv[RPB]          512
#define OFF_RED  (131072 + 1024)         // float4 red[16][64]     16384
#define OFF_U    (131072 + 1024 + 16384) // float u[256]           1024
#define OFF_S    (OFF_U + 1024)          // float s[64]            256
#define OFF_W    (OFF_S + 256)           // float wv[256]          1024
#define OFF_MISC (OFF_W + 1024)          // float misc[4]          16
#define SMEM_BYTES (OFF_MISC + 16)       // ~150 KB (< 227 KB opt-in)

// Deterministic scratch (fixed-slot writes, fixed-order reads)
__device__ float4 g_part4[BB][BPB][EE / 4];
__device__ float  g_vpart[BB][BPB];
// Graph-replay-safe grid barrier state
__device__ unsigned g_cnt = 0;
__device__ unsigned g_gen = 0;

__device__ __forceinline__ float4 ldcg4(const float4* p) {
    float4 r;
    asm volatile("ld.global.cg.v4.f32 {%0,%1,%2,%3}, [%4];"
                 : "=f"(r.x), "=f"(r.y), "=f"(r.z), "=f"(r.w) : "l"(p));
    return r;
}

__global__ void __launch_bounds__(1024, 1)
k_fused(const float* __restrict__ val, const int* __restrict__ pos,
        const float* __restrict__ embed, const float* __restrict__ Wq,
        const float* __restrict__ bq, const float* __restrict__ Wk,
        const float* __restrict__ bk, float* __restrict__ out) {
    const int blk  = blockIdx.x;
    const int b    = blk >> 5;        // batch
    const int ch   = blk & 31;        // chunk within batch
    const int t    = threadIdx.x;
    const int g    = t >> 6;          // 16 groups of 64 lanes
    const int l    = t & 63;
    const int warp = t >> 5;
    const int lane = t & 31;

    extern __shared__ char smem[];
    float4* srow = (float4*)(smem + OFF_SROW);   // [RPB][64]
    int*    sp   = (int*)   (smem + OFF_SP);
    float*  sv   = (float*) (smem + OFF_SV);
    float4* red  = (float4*)(smem + OFF_RED);    // [16][64]
    float*  u    = (float*) (smem + OFF_U);
    float*  sd   = (float*) (smem + OFF_S);
    float*  wv   = (float*) (smem + OFF_W);
    float*  misc = (float*) (smem + OFF_MISC);   // [0]=V, [1]=c

    // Snapshot generation BEFORE this block can possibly arrive at the barrier.
    const unsigned gen0 = *(volatile unsigned*)&g_gen;

    if (t < RPB) {
        sp[t] = pos[b * NN + ch * RPB + t];
        sv[t] = val[b * NN + ch * RPB + t];
    }
    __syncthreads();

    // ---- Phase 1: gather 8 rows/group in two 4-wide MLP batches,
    //      cache rows in smem, weighted-accumulate.
    float4 acc = make_float4(0.f, 0.f, 0.f, 0.f);
#pragma unroll
    for (int half = 0; half < 2; half++) {
        float4 a[4];
#pragma unroll
        for (int i = 0; i < 4; i++) {           // 4 independent LDG.128 in flight
            const int r = g * 8 + half * 4 + i;
            a[i] = __ldg((const float4*)(embed + (size_t)sp[r] * EE) + l);
        }
#pragma unroll
        for (int i = 0; i < 4; i++) {
            const int r = g * 8 + half * 4 + i;
            srow[r * 64 + l] = a[i];
            const float v = sv[r];
            acc.x += v * a[i].x; acc.y += v * a[i].y;
            acc.z += v * a[i].z; acc.w += v * a[i].w;
        }
    }
    red[g * 64 + l] = acc;
    __syncthreads();

    if (t < 64) {
        float4 s0 = red[t];
#pragma unroll
        for (int j = 1; j < 16; j++) {
            const float4 r4 = red[j * 64 + t];
            s0.x += r4.x; s0.y += r4.y; s0.z += r4.z; s0.w += r4.w;
        }
        g_part4[b][ch][t] = s0;
    }
    if (t == 1023) {
        float s = 0.f;
#pragma unroll
        for (int i = 0; i < RPB; i++) s += sv[i];
        g_vpart[b][ch] = s;
    }

    // ---- Grid barrier (graph-replay safe: monotonic generation counter)
    __threadfence();
    __syncthreads();
    if (t == 0) {
        const unsigned my = atomicAdd(&g_cnt, 1);
        if (my == NBLK - 1) {
            g_cnt = 0;                   // all NBLK have arrived; safe to reset
            __threadfence();
            atomicAdd(&g_gen, 1);
        } else {
            while (*(volatile unsigned*)&g_gen == gen0) {}
        }
        __threadfence();
    }
    __syncthreads();

    // ---- Phase 2 (redundant per block, for its own batch b)
    float4 a2 = make_float4(0.f, 0.f, 0.f, 0.f);
#pragma unroll
    for (int c = g; c < BPB; c += 16) {
        const float4 p4 = ldcg4(&g_part4[b][c][l]);
        a2.x += p4.x; a2.y += p4.y; a2.z += p4.z; a2.w += p4.w;
    }
    red[g * 64 + l] = a2;
    if (warp == 31) {
        float v = 0.f;
        if (lane < BPB) {
            asm volatile("ld.global.cg.f32 %0, [%1];" : "=f"(v) : "l"(&g_vpart[b][lane]));
        }
#pragma unroll
        for (int o = 16; o; o >>= 1) v += __shfl_xor_sync(0xffffffffu, v, o);
        if (lane == 0) misc[0] = v;
    }
    __syncthreads();

    if (t < 64) {
        float4 a = red[t];
#pragma unroll
        for (int j = 1; j < 16; j++) {
            const float4 r4 = red[j * 64 + t];
            a.x += r4.x; a.y += r4.y; a.z += r4.z; a.w += r4.w;
        }
        u[t * 4 + 0] = a.x; u[t * 4 + 1] = a.y;
        u[t * 4 + 2] = a.z; u[t * 4 + 3] = a.w;
    }
    __syncthreads();

    // s[d] = Wq[d,:] . u + bq[d]*V   (2 outputs per warp)
    const float V = misc[0];
#pragma unroll
    for (int d = warp; d < DD; d += 32) {
        float a = 0.f;
#pragma unroll
        for (int e = lane; e < EE; e += 32) a += __ldg(&Wq[d * EE + e]) * u[e];
#pragma unroll
        for (int o = 16; o; o >>= 1) a += __shfl_xor_sync(0xffffffffu, a, o);
        if (lane == 0) sd[d] = a + __ldg(&bq[d]) * V;
    }
    __syncthreads();

    // wv[t] = sum_d Wk[d][t]*s[d]   (coalesced);  c = s . bk (warp 30)
    if (t < EE) {
        float w = 0.f;
#pragma unroll 8
        for (int d = 0; d < DD; d++) w += __ldg(&Wk[d * EE + t]) * sd[d];
        wv[t] = w;
    }
    if (warp == 30) {
        float c = sd[lane] * __ldg(&bk[lane]) + sd[lane + 32] * __ldg(&bk[lane + 32]);
#pragma unroll
        for (int o = 16; o; o >>= 1) c += __shfl_xor_sync(0xffffffffu, c, o);
        if (lane == 0) misc[1] = c;
    }
    __syncthreads();

    // ---- Phase 3: rows from smem cache; 32 warps x 4 rows (no global gather)
    const float4 w0 = ((const float4*)wv)[lane];
    const float4 w1 = ((const float4*)wv)[lane + 32];
    const float  cs = misc[1];
#pragma unroll
    for (int i = 0; i < 4; i++) {
        const int r = warp * 4 + i;
        const float4 a0 = srow[r * 64 + lane];
        const float4 a1 = srow[r * 64 + lane + 32];
        float dot = a0.x * w0.x + a0.y * w0.y + a0.z * w0.z + a0.w * w0.w
                  + a1.x * w1.x + a1.y * w1.y + a1.z * w1.z + a1.w * w1.w;
#pragma unroll
        for (int o = 16; o; o >>= 1) dot += __shfl_xor_sync(0xffffffffu, dot, o);
        if (lane == 0) {
            const float v = sv[r];
            out[b * NN + ch * RPB + r] = v + v * (SCALE * (dot + cs));
        }
    }
}

// ---------------------------------------------------------------------------
extern "C" void kernel_launch(void* const* d_in, const int* in_sizes, int n_in,
                              void* d_out, int out_size) {
    // metadata order: t, val, pos, embed, Wq, bq, Wk, bk
    const int base = n_in - 7;
    const float* val   = (const float*)d_in[base + 0];
    const int*   pos   = (const int*)  d_in[base + 1];
    const float* embed = (const float*)d_in[base + 2];
    const float* Wq    = (const float*)d_in[base + 3];
    const float* bq    = (const float*)d_in[base + 4];
    const float* Wk    = (const float*)d_in[base + 5];
    const float* bk    = (const float*)d_in[base + 6];
    float* out = (float*)d_out;

    cudaFuncSetAttribute(k_fused, cudaFuncAttributeMaxDynamicSharedMemorySize,
                         SMEM_BYTES);
    k_fused<<<NBLK, 1024, SMEM_BYTES>>>(val, pos, embed, Wq, bq, Wk, bk, out);
}

// round 6
// speedup vs baseline: 2.1034x; 1.0259x over previous
#include <cuda_runtime.h>
#include <cstdint>

// cAttend_simple collapsed algebraically:
//   out[b,j] = val[b,j] * (1 + SCALE*(w_b . embed[pos[b,j]] + c_b))
//   s_b = Wq u_b + bq V_b;  u_b = sum_i val[b,i] embed[pos[b,i]];  V_b = sum_i val[b,i]
//   w_b = Wk^T s_b;  c_b = s_b . bk
//
// Single persistent kernel, 128 blocks x 1024 threads (1 CTA/SM, co-resident).
// Phase 1 gathers embed rows into a smem row-cache via cp.async (deep async
// pipeline, no register coupling); phase 3 reuses the cache (no 2nd gather).

#define BB 4
#define NN 4096
#define EE 256
#define DD 64
#define NBLK 128           // persistent blocks (<=148 SMs -> all resident)
#define BPB  32            // blocks per batch
#define RPB  128           // rows per block
#define SCALE 0.125f       // 64^{-1/2}

// smem layout (bytes)
#define OFF_SROW 0                       // float4 srow[RPB][64]   131072
#define OFF_SP   131072                  // int   sp[RPB]          512
#define OFF_SV   (131072 + 512)          // float sv[RPB]          512
#define OFF_RED  (131072 + 1024)         // float4 red[16][64]     16384
#define OFF_U    (131072 + 1024 + 16384) // float u[256]           1024
#define OFF_S    (OFF_U + 1024)          // float s[64]            256
#define OFF_W    (OFF_S + 256)           // float wv[256]          1024
#define OFF_MISC (OFF_W + 1024)          // float misc[4]          16
#define SMEM_BYTES (OFF_MISC + 16)       // ~150 KB (< 227 KB opt-in)

// Deterministic scratch (fixed-slot writes, fixed-order reads)
__device__ float4 g_part4[BB][BPB][EE / 4];
__device__ float  g_vpart[BB][BPB];
// Graph-replay-safe grid barrier state
__device__ unsigned g_cnt = 0;
__device__ unsigned g_gen = 0;

__device__ __forceinline__ float4 ldcg4(const float4* p) {
    float4 r;
    asm volatile("ld.global.cg.v4.f32 {%0,%1,%2,%3}, [%4];"
                 : "=f"(r.x), "=f"(r.y), "=f"(r.z), "=f"(r.w) : "l"(p));
    return r;
}

__device__ __forceinline__ void cp16(uint32_t dst_smem, const void* src) {
    asm volatile("cp.async.cg.shared.global [%0], [%1], 16;"
                 :: "r"(dst_smem), "l"(src));
}

__global__ void __launch_bounds__(1024, 1)
k_fused(const float* __restrict__ val, const int* __restrict__ pos,
        const float* __restrict__ embed, const float* __restrict__ Wq,
        const float* __restrict__ bq, const float* __restrict__ Wk,
        const float* __restrict__ bk, float* __restrict__ out) {
    const int blk  = blockIdx.x;
    const int b    = blk >> 5;        // batch
    const int ch   = blk & 31;        // chunk within batch
    const int t    = threadIdx.x;
    const int g    = t >> 6;          // 16 groups of 64 lanes
    const int l    = t & 63;
    const int warp = t >> 5;
    const int lane = t & 31;

    extern __shared__ char smem[];
    float4* srow = (float4*)(smem + OFF_SROW);   // [RPB][64]
    int*    sp   = (int*)   (smem + OFF_SP);
    float*  sv   = (float*) (smem + OFF_SV);
    float4* red  = (float4*)(smem + OFF_RED);    // [16][64]
    float*  u    = (float*) (smem + OFF_U);
    float*  sd   = (float*) (smem + OFF_S);
    float*  wv   = (float*) (smem + OFF_W);
    float*  misc = (float*) (smem + OFF_MISC);   // [0]=V, [1]=c

    uint32_t smem_u32;
    {
        uint64_t tmp;
        asm("cvta.to.shared.u64 %0, %1;" : "=l"(tmp) : "l"(smem));
        smem_u32 = (uint32_t)tmp;
    }

    // Snapshot generation BEFORE this block can possibly arrive at the barrier.
    const unsigned gen0 = *(volatile unsigned*)&g_gen;

    if (t < RPB) {
        sp[t] = pos[b * NN + ch * RPB + t];
        sv[t] = val[b * NN + ch * RPB + t];
    }
    __syncthreads();

    // ---- Phase 1: async-gather all 8 rows/group into the smem row cache.
    // No registers involved -> all 8 copies in flight per thread at once.
    {
        const uint32_t srow_base = smem_u32 + OFF_SROW;
#pragma unroll
        for (int i = 0; i < 8; i++) {
            const int r = g * 8 + i;
            cp16(srow_base + (uint32_t)(r * 64 + l) * 16u,
                 embed + (size_t)sp[r] * EE + l * 4);
        }
        asm volatile("cp.async.commit_group;" ::: "memory");
    }

    // Overlap: V partial sum while copies are in flight (warp 31 only)
    if (t == 1023) {
        float s = 0.f;
#pragma unroll
        for (int i = 0; i < RPB; i++) s += sv[i];
        g_vpart[b][ch] = s;
    }

    asm volatile("cp.async.wait_group 0;" ::: "memory");
    __syncthreads();

    // Weighted accumulate from the smem cache (LDS.128, pipelined)
    float4 acc = make_float4(0.f, 0.f, 0.f, 0.f);
#pragma unroll
    for (int i = 0; i < 8; i++) {
        const int r = g * 8 + i;
        const float4 a = srow[r * 64 + l];
        const float v = sv[r];
        acc.x += v * a.x; acc.y += v * a.y; acc.z += v * a.z; acc.w += v * a.w;
    }
    red[g * 64 + l] = acc;
    __syncthreads();

    if (t < 64) {
        float4 s0 = red[t];
#pragma unroll
        for (int j = 1; j < 16; j++) {
            const float4 r4 = red[j * 64 + t];
            s0.x += r4.x; s0.y += r4.y; s0.z += r4.z; s0.w += r4.w;
        }
        g_part4[b][ch][t] = s0;
    }

    // ---- Grid barrier (graph-replay safe: monotonic generation counter)
    __threadfence();
    __syncthreads();
    if (t == 0) {
        const unsigned my = atomicAdd(&g_cnt, 1);
        if (my == NBLK - 1) {
            g_cnt = 0;                   // all NBLK have arrived; safe to reset
            __threadfence();
            atomicAdd(&g_gen, 1);
        } else {
            while (*(volatile unsigned*)&g_gen == gen0) { __nanosleep(64); }
        }
        __threadfence();
    }
    __syncthreads();

    // ---- Phase 2 (redundant per block, for its own batch b)
    float4 a2 = make_float4(0.f, 0.f, 0.f, 0.f);
#pragma unroll
    for (int c = g; c < BPB; c += 16) {
        const float4 p4 = ldcg4(&g_part4[b][c][l]);
        a2.x += p4.x; a2.y += p4.y; a2.z += p4.z; a2.w += p4.w;
    }
    red[g * 64 + l] = a2;
    if (warp == 31) {
        float v = 0.f;
        if (lane < BPB) {
            asm volatile("ld.global.cg.f32 %0, [%1];" : "=f"(v) : "l"(&g_vpart[b][lane]));
        }
#pragma unroll
        for (int o = 16; o; o >>= 1) v += __shfl_xor_sync(0xffffffffu, v, o);
        if (lane == 0) misc[0] = v;
    }
    __syncthreads();

    if (t < 64) {
        float4 a = red[t];
#pragma unroll
        for (int j = 1; j < 16; j++) {
            const float4 r4 = red[j * 64 + t];
            a.x += r4.x; a.y += r4.y; a.z += r4.z; a.w += r4.w;
        }
        u[t * 4 + 0] = a.x; u[t * 4 + 1] = a.y;
        u[t * 4 + 2] = a.z; u[t * 4 + 3] = a.w;
    }
    __syncthreads();

    // s[d] = Wq[d,:] . u + bq[d]*V   (2 outputs per warp)
    const float V = misc[0];
#pragma unroll
    for (int d = warp; d < DD; d += 32) {
        float a = 0.f;
#pragma unroll
        for (int e = lane; e < EE; e += 32) a += __ldg(&Wq[d * EE + e]) * u[e];
#pragma unroll
        for (int o = 16; o; o >>= 1) a += __shfl_xor_sync(0xffffffffu, a, o);
        if (lane == 0) sd[d] = a + __ldg(&bq[d]) * V;
    }
    __syncthreads();

    // wv[t] = sum_d Wk[d][t]*s[d]   (coalesced);  c = s . bk (warp 30)
    if (t < EE) {
        float w = 0.f;
#pragma unroll 8
        for (int d = 0; d < DD; d++) w += __ldg(&Wk[d * EE + t]) * sd[d];
        wv[t] = w;
    }
    if (warp == 30) {
        float c = sd[lane] * __ldg(&bk[lane]) + sd[lane + 32] * __ldg(&bk[lane + 32]);
#pragma unroll
        for (int o = 16; o; o >>= 1) c += __shfl_xor_sync(0xffffffffu, c, o);
        if (lane == 0) misc[1] = c;
    }
    __syncthreads();

    // ---- Phase 3: rows from smem cache; 32 warps x 4 rows (no global gather)
    const float4 w0 = ((const float4*)wv)[lane];
    const float4 w1 = ((const float4*)wv)[lane + 32];
    const float  cs = misc[1];
#pragma unroll
    for (int i = 0; i < 4; i++) {
        const int r = warp * 4 + i;
        const float4 a0 = srow[r * 64 + lane];
        const float4 a1 = srow[r * 64 + lane + 32];
        float dot = a0.x * w0.x + a0.y * w0.y + a0.z * w0.z + a0.w * w0.w
                  + a1.x * w1.x + a1.y * w1.y + a1.z * w1.z + a1.w * w1.w;
#pragma unroll
        for (int o = 16; o; o >>= 1) dot += __shfl_xor_sync(0xffffffffu, dot, o);
        if (lane == 0) {
            const float v = sv[r];
            out[b * NN + ch * RPB + r] = v + v * (SCALE * (dot + cs));
        }
    }
}

// ---------------------------------------------------------------------------
extern "C" void kernel_launch(void* const* d_in, const int* in_sizes, int n_in,
                              void* d_out, int out_size) {
    // metadata order: t, val, pos, embed, Wq, bq, Wk, bk
    const int base = n_in - 7;
    const float* val   = (const float*)d_in[base + 0];
    const int*   pos   = (const int*)  d_in[base + 1];
    const float* embed = (const float*)d_in[base + 2];
    const float* Wq    = (const float*)d_in[base + 3];
    const float* bq    = (const float*)d_in[base + 4];
    const float* Wk    = (const float*)d_in[base + 5];
    const float* bk    = (const float*)d_in[base + 6];
    float* out = (float*)d_out;

    cudaFuncSetAttribute(k_fused, cudaFuncAttributeMaxDynamicSharedMemorySize,
                         SMEM_BYTES);
    k_fused<<<NBLK, 1024, SMEM_BYTES>>>(val, pos, embed, Wq, bq, Wk, bk, out);
}